// round 9
// baseline (speedup 1.0000x reference)
#include <cuda_runtime.h>
#include <cuda_bf16.h>
#include <cstdint>
#include <math.h>

#define BSZ   2048
#define NTOT  4096
#define DDIM  256
#define INV_T 2.0f
#define NTILE 32
#define NTRI  528            // upper-triangular 128x128 tiles
#define BKS   64             // K per stage
#define NKT   4              // DDIM / BKS
#define BUFB  32768          // per-ring-buffer bytes: A(16K) + B(16K)
#define SMEM_TOTAL (3 * BUFB)

// Scratch (device globals; no allocation allowed)
__device__ uint4  g_znb4[NTOT * DDIM / 8];
__device__ float  g_rowsum[NTOT];
__device__ float  g_pos[NTOT];
__device__ unsigned g_done;

// ---------------------------------------------------------------------------
// Kernel 1: L2-normalize rows -> bf16; zero accumulators + completion counter
// ---------------------------------------------------------------------------
__global__ __launch_bounds__(256) void nt_normalize(const float* __restrict__ zi,
                                                    const float* __restrict__ zj) {
    int row  = (blockIdx.x * blockDim.x + threadIdx.x) >> 5;
    int lane = threadIdx.x & 31;
    if (blockIdx.x == 0 && threadIdx.x == 0) g_done = 0u;
    if (row >= NTOT) return;

    const float* src = (row < BSZ) ? (zi + (size_t)row * DDIM)
                                   : (zj + (size_t)(row - BSZ) * DDIM);
    const float4* s4 = (const float4*)src;
    float4 a = s4[lane];
    float4 b = s4[lane + 32];

    float ss = a.x*a.x + a.y*a.y + a.z*a.z + a.w*a.w
             + b.x*b.x + b.y*b.y + b.z*b.z + b.w*b.w;
#pragma unroll
    for (int o = 16; o; o >>= 1) ss += __shfl_xor_sync(0xFFFFFFFFu, ss, o);

    float inv = 1.0f / fmaxf(sqrtf(ss), 1e-8f);

    __nv_bfloat162* d2 = (__nv_bfloat162*)((__nv_bfloat16*)g_znb4 + (size_t)row * DDIM);
    d2[2*lane]          = __nv_bfloat162(__float2bfloat16(a.x*inv), __float2bfloat16(a.y*inv));
    d2[2*lane + 1]      = __nv_bfloat162(__float2bfloat16(a.z*inv), __float2bfloat16(a.w*inv));
    d2[64 + 2*lane]     = __nv_bfloat162(__float2bfloat16(b.x*inv), __float2bfloat16(b.y*inv));
    d2[64 + 2*lane + 1] = __nv_bfloat162(__float2bfloat16(b.z*inv), __float2bfloat16(b.w*inv));

    if (lane == 0) g_rowsum[row] = 0.0f;
}

// ---------------------------------------------------------------------------
// Helpers
// ---------------------------------------------------------------------------
__device__ __forceinline__ void cp_async16(uint32_t s, const void* g) {
    asm volatile("cp.async.cg.shared.global [%0], [%1], 16;\n" :: "r"(s), "l"(g));
}
__device__ __forceinline__ void cp_commit() { asm volatile("cp.async.commit_group;\n"); }
__device__ __forceinline__ void cp_wait1()  { asm volatile("cp.async.wait_group 1;\n"); }
__device__ __forceinline__ void cp_wait0()  { asm volatile("cp.async.wait_group 0;\n"); }
__device__ __forceinline__ void ldm_x4(uint32_t addr, uint32_t& r0, uint32_t& r1,
                                       uint32_t& r2, uint32_t& r3) {
    asm volatile("ldmatrix.sync.aligned.m8n8.x4.shared.b16 {%0,%1,%2,%3}, [%4];\n"
                 : "=r"(r0), "=r"(r1), "=r"(r2), "=r"(r3) : "r"(addr));
}
__device__ __forceinline__ void mma16816(float& d0, float& d1, float& d2, float& d3,
                                         uint32_t a0, uint32_t a1, uint32_t a2, uint32_t a3,
                                         uint32_t b0, uint32_t b1) {
    asm volatile("mma.sync.aligned.m16n8k16.row.col.f32.bf16.bf16.f32 "
                 "{%0,%1,%2,%3}, {%4,%5,%6,%7}, {%8,%9}, {%0,%1,%2,%3};\n"
                 : "+f"(d0), "+f"(d1), "+f"(d2), "+f"(d3)
                 : "r"(a0), "r"(a1), "r"(a2), "r"(a3), "r"(b0), "r"(b1));
}
__device__ __forceinline__ uint32_t sw128(uint32_t off) {   // 16B-granular XOR swizzle
    return off ^ ((off >> 3) & 0x70);
}

// ---------------------------------------------------------------------------
// Kernel 2: bf16 mma.sync GEMM on upper-triangular tiles. 3-stage cp.async
// ring (1 barrier/stage), software-pipelined ldmatrix fragments, specialized
// epilogue + last-CTA finalize.
// ---------------------------------------------------------------------------
__global__ __launch_bounds__(256, 2) void nt_mma(float* __restrict__ out) {
    extern __shared__ __align__(1024) char smem[];
    uint32_t sb;
    asm("{ .reg .u64 t; cvta.to.shared.u64 t, %1; cvt.u32.u64 %0, t; }"
        : "=r"(sb) : "l"((const void*)smem));

    // decode upper-triangular tile index -> (bi, bj), bi <= bj
    int t = blockIdx.x, bi = 0;
    while (t >= NTILE - bi) { t -= NTILE - bi; bi++; }
    const int bj = bi + t;
    const bool diag    = (bi == bj);
    const bool posTile = (bj - bi == 16);   // only these contain positive pairs
    const int rowBase = bi * 128;
    const int colBase = bj * 128;

    const int tid  = threadIdx.x;
    const int wid  = tid >> 5;
    const int lane = tid & 31;
    const int warp_m = wid & 3;      // 32 rows each
    const int warp_n = wid >> 2;     // 64 cols each

    const __nv_bfloat16* Z = (const __nv_bfloat16*)g_znb4;

    float acc[2][8][4];
#pragma unroll
    for (int mi = 0; mi < 2; mi++)
#pragma unroll
        for (int ni = 0; ni < 8; ni++)
#pragma unroll
            for (int r = 0; r < 4; r++) acc[mi][ni][r] = 0.0f;

    // stage loader into ring buffer st%3; diag tiles skip the B half (B==A)
    auto load_stage = [&](int st) {
        const uint32_t base = sb + (uint32_t)(st % 3) * BUFB;
        const int nl = diag ? 4 : 8;
        for (int l = 0; l < nl; l++) {
            int ch  = tid + l * 256;
            int isB = ch >> 10;
            int idx = ch & 1023;
            int r = idx >> 3, c = idx & 7;
            uint32_t dst = base + isB * 16384 + sw128((uint32_t)(r * 128 + c * 16));
            const void* src = Z + (size_t)((isB ? colBase : rowBase) + r) * DDIM
                            + st * BKS + c * 8;
            cp_async16(dst, src);
        }
        cp_commit();
    };

    // fragment loaders
    auto ldA = [&](uint32_t aBase, int ks, uint32_t a[2][4]) {
#pragma unroll
        for (int mi = 0; mi < 2; mi++) {
            int r = warp_m * 32 + mi * 16 + (lane & 15);
            uint32_t ad = aBase + sw128((uint32_t)(r * 128 + ks * 32 + (lane >> 4) * 16));
            ldm_x4(ad, a[mi][0], a[mi][1], a[mi][2], a[mi][3]);
        }
    };
    auto ldB = [&](uint32_t bBase, int ks, uint32_t b[8][2]) {
#pragma unroll
        for (int p = 0; p < 4; p++) {
            int nrow = warp_n * 64 + p * 16 + (lane >> 4) * 8 + (lane & 7);
            uint32_t ad = bBase + sw128((uint32_t)(nrow * 128 + ks * 32 + ((lane >> 3) & 1) * 16));
            uint32_t r0, r1, r2, r3;
            ldm_x4(ad, r0, r1, r2, r3);
            b[2*p][0] = r0;   b[2*p][1] = r1;
            b[2*p+1][0] = r2; b[2*p+1][1] = r3;
        }
    };

    load_stage(0);
    load_stage(1);

    for (int st = 0; st < NKT; st++) {
        if (st < NKT - 1) cp_wait1(); else cp_wait0();
        __syncthreads();                       // stage st visible; st-1 reads done everywhere
        if (st + 2 < NKT) load_stage(st + 2);  // slot (st+2)%3 freed by the barrier above

        const uint32_t aBase = sb + (uint32_t)(st % 3) * BUFB;
        const uint32_t bBase = diag ? aBase : (aBase + 16384);

        uint32_t af[2][2][4], bf[2][8][2];
        ldA(aBase, 0, af[0]);
        ldB(bBase, 0, bf[0]);
#pragma unroll
        for (int ks = 0; ks < 4; ks++) {
            const int cur = ks & 1, nxt = cur ^ 1;
            if (ks < 3) { ldA(aBase, ks + 1, af[nxt]); ldB(bBase, ks + 1, bf[nxt]); }
#pragma unroll
            for (int mi = 0; mi < 2; mi++)
#pragma unroll
                for (int ni = 0; ni < 8; ni++)
                    mma16816(acc[mi][ni][0], acc[mi][ni][1], acc[mi][ni][2], acc[mi][ni][3],
                             af[cur][mi][0], af[cur][mi][1], af[cur][mi][2], af[cur][mi][3],
                             bf[cur][ni][0], bf[cur][ni][1]);
        }
    }

    // ---- Epilogue, specialized per tile type.
    float colsum[8][2];
#pragma unroll
    for (int ni = 0; ni < 8; ni++) { colsum[ni][0] = 0.0f; colsum[ni][1] = 0.0f; }

#pragma unroll
    for (int mi = 0; mi < 2; mi++) {
#pragma unroll
        for (int half = 0; half < 2; half++) {
            int row = rowBase + warp_m * 32 + mi * 16 + half * 8 + (lane >> 2);
            float s = 0.0f;
            if (diag) {
#pragma unroll
                for (int ni = 0; ni < 8; ni++)
#pragma unroll
                    for (int cc = 0; cc < 2; cc++) {
                        int col = colBase + warp_n * 64 + ni * 8 + 2 * (lane & 3) + cc;
                        float v = acc[mi][ni][half * 2 + cc] * INV_T;
                        if (col != row) s += __expf(v - 2.0f);
                    }
            } else if (posTile) {
#pragma unroll
                for (int ni = 0; ni < 8; ni++)
#pragma unroll
                    for (int cc = 0; cc < 2; cc++) {
                        int col = colBase + warp_n * 64 + ni * 8 + 2 * (lane & 3) + cc;
                        float v = acc[mi][ni][half * 2 + cc] * INV_T;
                        if (col == row + BSZ) { g_pos[row] = v; g_pos[col] = v; }
                        float e = __expf(v - 2.0f);
                        s += e;
                        colsum[ni][cc] += e;
                    }
            } else {
#pragma unroll
                for (int ni = 0; ni < 8; ni++)
#pragma unroll
                    for (int cc = 0; cc < 2; cc++) {
                        float e = __expf(acc[mi][ni][half * 2 + cc] * INV_T - 2.0f);
                        s += e;
                        colsum[ni][cc] += e;
                    }
            }
            s += __shfl_xor_sync(0xFFFFFFFFu, s, 1);
            s += __shfl_xor_sync(0xFFFFFFFFu, s, 2);
            if ((lane & 3) == 0) atomicAdd(&g_rowsum[row], s);
        }
    }

    if (!diag) {
#pragma unroll
        for (int ni = 0; ni < 8; ni++) {
#pragma unroll
            for (int cc = 0; cc < 2; cc++) {
                float s = colsum[ni][cc];
                s += __shfl_xor_sync(0xFFFFFFFFu, s, 4);
                s += __shfl_xor_sync(0xFFFFFFFFu, s, 8);
                s += __shfl_xor_sync(0xFFFFFFFFu, s, 16);
                if (lane < 4) {
                    int col = colBase + warp_n * 64 + ni * 8 + 2 * lane + cc;
                    atomicAdd(&g_rowsum[col], s);
                }
            }
        }
    }

    // ---- last-CTA finalize
    __threadfence();
    __syncthreads();
    __shared__ unsigned s_last;
    if (tid == 0) s_last = (atomicAdd(&g_done, 1u) == NTRI - 1) ? 1u : 0u;
    __syncthreads();
    if (s_last) {
        __shared__ float red[256];
        float s = 0.0f;
        for (int i = tid; i < NTOT; i += 256)
            s += 2.0f + logf(__ldcg(&g_rowsum[i])) - __ldcg(&g_pos[i]);
        red[tid] = s;
        __syncthreads();
#pragma unroll
        for (int o = 128; o; o >>= 1) {
            if (tid < o) red[tid] += red[tid + o];
            __syncthreads();
        }
        if (tid == 0) out[0] = red[0] * (1.0f / NTOT);
    }
}

extern "C" void kernel_launch(void* const* d_in, const int* in_sizes, int n_in,
                              void* d_out, int out_size) {
    const float* zi = (const float*)d_in[0];
    const float* zj = (const float*)d_in[1];
    float* out = (float*)d_out;
    (void)in_sizes; (void)n_in; (void)out_size;

    cudaFuncSetAttribute(nt_mma, cudaFuncAttributeMaxDynamicSharedMemorySize, SMEM_TOTAL);

    nt_normalize<<<NTOT / 8, 256>>>(zi, zj);
    nt_mma<<<NTRI, 256, SMEM_TOTAL>>>(out);
}

// round 10
// speedup vs baseline: 1.0656x; 1.0656x over previous
#include <cuda_runtime.h>
#include <cuda_bf16.h>
#include <cstdint>
#include <math.h>

#define BSZ   2048
#define NTOT  4096
#define DDIM  256
#define NTILE 32
#define NTRI  528            // upper-triangular 128x128 tiles
#define BKS   64             // K per stage
#define BUFB  32768          // ring buffer: A(16K) + B(16K)
#define SMEM_TOTAL (3 * BUFB)
#define L2E2  2.885390081777927f   // 2*log2(e)

// Scratch (device globals; no allocation allowed)
__device__ uint4  g_znb4[NTOT * DDIM / 8];
__device__ float  g_rowsum[NTOT];
__device__ float  g_pos[NTOT];
__device__ unsigned g_done;

// ---------------------------------------------------------------------------
// Kernel 1: L2-normalize rows -> bf16; zero accumulators + completion counter
// ---------------------------------------------------------------------------
__global__ __launch_bounds__(256) void nt_normalize(const float* __restrict__ zi,
                                                    const float* __restrict__ zj) {
    int row  = (blockIdx.x * blockDim.x + threadIdx.x) >> 5;
    int lane = threadIdx.x & 31;
    if (blockIdx.x == 0 && threadIdx.x == 0) g_done = 0u;
    if (row >= NTOT) return;

    const float* src = (row < BSZ) ? (zi + (size_t)row * DDIM)
                                   : (zj + (size_t)(row - BSZ) * DDIM);
    const float4* s4 = (const float4*)src;
    float4 a = s4[lane];
    float4 b = s4[lane + 32];

    float ss = a.x*a.x + a.y*a.y + a.z*a.z + a.w*a.w
             + b.x*b.x + b.y*b.y + b.z*b.z + b.w*b.w;
#pragma unroll
    for (int o = 16; o; o >>= 1) ss += __shfl_xor_sync(0xFFFFFFFFu, ss, o);

    float inv = 1.0f / fmaxf(sqrtf(ss), 1e-8f);

    __nv_bfloat162* d2 = (__nv_bfloat162*)((__nv_bfloat16*)g_znb4 + (size_t)row * DDIM);
    d2[2*lane]          = __nv_bfloat162(__float2bfloat16(a.x*inv), __float2bfloat16(a.y*inv));
    d2[2*lane + 1]      = __nv_bfloat162(__float2bfloat16(a.z*inv), __float2bfloat16(a.w*inv));
    d2[64 + 2*lane]     = __nv_bfloat162(__float2bfloat16(b.x*inv), __float2bfloat16(b.y*inv));
    d2[64 + 2*lane + 1] = __nv_bfloat162(__float2bfloat16(b.z*inv), __float2bfloat16(b.w*inv));

    if (lane == 0) g_rowsum[row] = 0.0f;
}

// ---------------------------------------------------------------------------
// Helpers
// ---------------------------------------------------------------------------
__device__ __forceinline__ void cp_async16(uint32_t s, const void* g) {
    asm volatile("cp.async.cg.shared.global [%0], [%1], 16;\n" :: "r"(s), "l"(g));
}
__device__ __forceinline__ void cp_commit() { asm volatile("cp.async.commit_group;\n"); }
__device__ __forceinline__ void cp_wait1()  { asm volatile("cp.async.wait_group 1;\n"); }
__device__ __forceinline__ void cp_wait0()  { asm volatile("cp.async.wait_group 0;\n"); }
__device__ __forceinline__ void ldm_x4(uint32_t addr, uint32_t& r0, uint32_t& r1,
                                       uint32_t& r2, uint32_t& r3) {
    asm volatile("ldmatrix.sync.aligned.m8n8.x4.shared.b16 {%0,%1,%2,%3}, [%4];\n"
                 : "=r"(r0), "=r"(r1), "=r"(r2), "=r"(r3) : "r"(addr));
}
__device__ __forceinline__ void mma16816(float& d0, float& d1, float& d2, float& d3,
                                         uint32_t a0, uint32_t a1, uint32_t a2, uint32_t a3,
                                         uint32_t b0, uint32_t b1) {
    asm volatile("mma.sync.aligned.m16n8k16.row.col.f32.bf16.bf16.f32 "
                 "{%0,%1,%2,%3}, {%4,%5,%6,%7}, {%8,%9}, {%0,%1,%2,%3};\n"
                 : "+f"(d0), "+f"(d1), "+f"(d2), "+f"(d3)
                 : "r"(a0), "r"(a1), "r"(a2), "r"(a3), "r"(b0), "r"(b1));
}
__device__ __forceinline__ uint32_t sw128(uint32_t off) {
    return off ^ ((off >> 3) & 0x70);
}
__device__ __forceinline__ float ex2(float x) {
    float r;
    asm("ex2.approx.ftz.f32 %0, %1;" : "=f"(r) : "f"(x));
    return r;
}

// ---------------------------------------------------------------------------
// Kernel 2: bf16 mma.sync GEMM on upper-triangular tiles. 3-buffer cp.async
// ring, fully unrolled (compile-time buffer indices), 1 barrier/stage,
// specialized epilogue + last-CTA finalize.
// ---------------------------------------------------------------------------
__global__ __launch_bounds__(256, 2) void nt_mma(float* __restrict__ out) {
    extern __shared__ __align__(1024) char smem[];
    uint32_t sb;
    asm("{ .reg .u64 t; cvta.to.shared.u64 t, %1; cvt.u32.u64 %0, t; }"
        : "=r"(sb) : "l"((const void*)smem));

    // decode upper-triangular tile index -> (bi, bj), bi <= bj
    int t = blockIdx.x, bi = 0;
    while (t >= NTILE - bi) { t -= NTILE - bi; bi++; }
    const int bj = bi + t;
    const bool diag    = (bi == bj);
    const bool posTile = (bj - bi == 16);
    const int rowBase = bi * 128;
    const int colBase = bj * 128;

    const int tid  = threadIdx.x;
    const int wid  = tid >> 5;
    const int lane = tid & 31;
    const int warp_m = wid & 3;
    const int warp_n = wid >> 2;

    const __nv_bfloat16* Z = (const __nv_bfloat16*)g_znb4;

    float acc[2][8][4];
#pragma unroll
    for (int mi = 0; mi < 2; mi++)
#pragma unroll
        for (int ni = 0; ni < 8; ni++)
#pragma unroll
            for (int r = 0; r < 4; r++) acc[mi][ni][r] = 0.0f;

    // stage loader (compile-time buf); diag tiles skip B half (B==A)
    auto load_stage = [&](int st, int buf) {
        const uint32_t base = sb + (uint32_t)buf * BUFB;
        const int nl = diag ? 4 : 8;
        for (int l = 0; l < nl; l++) {
            int ch  = tid + l * 256;
            int isB = ch >> 10;
            int idx = ch & 1023;
            int r = idx >> 3, c = idx & 7;
            uint32_t dst = base + isB * 16384 + sw128((uint32_t)(r * 128 + c * 16));
            const void* src = Z + (size_t)((isB ? colBase : rowBase) + r) * DDIM
                            + st * BKS + c * 8;
            cp_async16(dst, src);
        }
        cp_commit();
    };

    // round-8 style per-stage MMA (no fragment double-buffer: fits 128 regs)
    auto mma_stage = [&](uint32_t aBase, uint32_t bBase) {
#pragma unroll
        for (int ks = 0; ks < 4; ks++) {
            uint32_t a[2][4];
#pragma unroll
            for (int mi = 0; mi < 2; mi++) {
                int r = warp_m * 32 + mi * 16 + (lane & 15);
                uint32_t ad = aBase + sw128((uint32_t)(r * 128 + ks * 32 + (lane >> 4) * 16));
                ldm_x4(ad, a[mi][0], a[mi][1], a[mi][2], a[mi][3]);
            }
            uint32_t b[8][2];
#pragma unroll
            for (int p = 0; p < 4; p++) {
                int nrow = warp_n * 64 + p * 16 + (lane >> 4) * 8 + (lane & 7);
                uint32_t ad = bBase + sw128((uint32_t)(nrow * 128 + ks * 32 + ((lane >> 3) & 1) * 16));
                uint32_t r0, r1, r2, r3;
                ldm_x4(ad, r0, r1, r2, r3);
                b[2*p][0] = r0;   b[2*p][1] = r1;
                b[2*p+1][0] = r2; b[2*p+1][1] = r3;
            }
#pragma unroll
            for (int mi = 0; mi < 2; mi++)
#pragma unroll
                for (int ni = 0; ni < 8; ni++)
                    mma16816(acc[mi][ni][0], acc[mi][ni][1], acc[mi][ni][2], acc[mi][ni][3],
                             a[mi][0], a[mi][1], a[mi][2], a[mi][3],
                             b[ni][0], b[ni][1]);
        }
    };

    const uint32_t A0 = sb, A1 = sb + BUFB, A2 = sb + 2 * BUFB;
    const uint32_t bOfs = diag ? 0u : 16384u;

    load_stage(0, 0);
    load_stage(1, 1);
    // stage 0
    cp_wait1(); __syncthreads();
    load_stage(2, 2);
    mma_stage(A0, A0 + bOfs);
    // stage 1
    cp_wait1(); __syncthreads();
    load_stage(3, 0);                 // buf0: reads finished by all warps at this barrier
    mma_stage(A1, A1 + bOfs);
    // stage 2
    cp_wait1(); __syncthreads();
    mma_stage(A2, A2 + bOfs);
    // stage 3
    cp_wait0(); __syncthreads();
    mma_stage(A0, A0 + bOfs);

    // ---- Epilogue, specialized per tile type. exp(2a-2) = ex2(fma(a,L2E2,-L2E2))
    float colsum[8][2];
#pragma unroll
    for (int ni = 0; ni < 8; ni++) { colsum[ni][0] = 0.0f; colsum[ni][1] = 0.0f; }

#pragma unroll
    for (int mi = 0; mi < 2; mi++) {
#pragma unroll
        for (int half = 0; half < 2; half++) {
            int row = rowBase + warp_m * 32 + mi * 16 + half * 8 + (lane >> 2);
            float s = 0.0f;
            if (diag) {
#pragma unroll
                for (int ni = 0; ni < 8; ni++)
#pragma unroll
                    for (int cc = 0; cc < 2; cc++) {
                        int col = colBase + warp_n * 64 + ni * 8 + 2 * (lane & 3) + cc;
                        float e = ex2(fmaf(acc[mi][ni][half * 2 + cc], L2E2, -L2E2));
                        if (col != row) s += e;
                    }
            } else if (posTile) {
#pragma unroll
                for (int ni = 0; ni < 8; ni++)
#pragma unroll
                    for (int cc = 0; cc < 2; cc++) {
                        int col = colBase + warp_n * 64 + ni * 8 + 2 * (lane & 3) + cc;
                        float av = acc[mi][ni][half * 2 + cc];
                        if (col == row + BSZ) {
                            float v = av * 2.0f;
                            g_pos[row] = v; g_pos[col] = v;
                        }
                        float e = ex2(fmaf(av, L2E2, -L2E2));
                        s += e;
                        colsum[ni][cc] += e;
                    }
            } else {
#pragma unroll
                for (int ni = 0; ni < 8; ni++)
#pragma unroll
                    for (int cc = 0; cc < 2; cc++) {
                        float e = ex2(fmaf(acc[mi][ni][half * 2 + cc], L2E2, -L2E2));
                        s += e;
                        colsum[ni][cc] += e;
                    }
            }
            s += __shfl_xor_sync(0xFFFFFFFFu, s, 1);
            s += __shfl_xor_sync(0xFFFFFFFFu, s, 2);
            if ((lane & 3) == 0) atomicAdd(&g_rowsum[row], s);
        }
    }

    if (!diag) {
#pragma unroll
        for (int ni = 0; ni < 8; ni++) {
#pragma unroll
            for (int cc = 0; cc < 2; cc++) {
                float s = colsum[ni][cc];
                s += __shfl_xor_sync(0xFFFFFFFFu, s, 4);
                s += __shfl_xor_sync(0xFFFFFFFFu, s, 8);
                s += __shfl_xor_sync(0xFFFFFFFFu, s, 16);
                if (lane < 4) {
                    int col = colBase + warp_n * 64 + ni * 8 + 2 * lane + cc;
                    atomicAdd(&g_rowsum[col], s);
                }
            }
        }
    }

    // ---- last-CTA finalize
    __threadfence();
    __syncthreads();
    __shared__ unsigned s_last;
    if (tid == 0) s_last = (atomicAdd(&g_done, 1u) == NTRI - 1) ? 1u : 0u;
    __syncthreads();
    if (s_last) {
        __shared__ float red[256];
        float s = 0.0f;
        for (int i = tid; i < NTOT; i += 256)
            s += 2.0f + logf(__ldcg(&g_rowsum[i])) - __ldcg(&g_pos[i]);
        red[tid] = s;
        __syncthreads();
#pragma unroll
        for (int o = 128; o; o >>= 1) {
            if (tid < o) red[tid] += red[tid + o];
            __syncthreads();
        }
        if (tid == 0) out[0] = red[0] * (1.0f / NTOT);
    }
}

extern "C" void kernel_launch(void* const* d_in, const int* in_sizes, int n_in,
                              void* d_out, int out_size) {
    const float* zi = (const float*)d_in[0];
    const float* zj = (const float*)d_in[1];
    float* out = (float*)d_out;
    (void)in_sizes; (void)n_in; (void)out_size;

    cudaFuncSetAttribute(nt_mma, cudaFuncAttributeMaxDynamicSharedMemorySize, SMEM_TOTAL);

    nt_normalize<<<NTOT / 8, 256>>>(zi, zj);
    nt_mma<<<NTRI, 256, SMEM_TOTAL>>>(out);
}